// round 2
// baseline (speedup 1.0000x reference)
#include <cuda_runtime.h>

// ---------------------------------------------------------------------------
// GCN 5-layer forward on GB300.
// Per-launch CSR build (hist -> block-scan offset alloc -> scatter), then per
// layer: dense transform fused with dinv[row] pre-scale, and a warp-per-
// destination-node gather (lane = feature) that is L2-bandwidth bound.
// Edge index dtype (int32 vs int64) is probed on device each launch.
// ---------------------------------------------------------------------------

#define NN 100000
#define NE 1600000

__device__ int   g_deg[NN];        // edge in-degree (without self loop)
__device__ int   g_off[NN];        // start offsets, mutated to end by scatter
__device__ int   g_rows[NE];       // CSR row (source) indices grouped by col
__device__ float g_gbuf[NN * 32];  // dinv[n] * (H W) rows
__device__ float g_hbuf[NN * 32];  // layer activations
__device__ int   g_alloc;          // offset range allocator
__device__ int   g_is64;           // 1 if edge_index is int64, 0 if int32

// Probe dtype: interpret first 256 entries as int64. True int64 node ids are
// all in [0, NN); int32 data read as int64 packs two ids -> huge values.
__global__ void k_detect(const long long* __restrict__ ei) {
    __shared__ int bad;
    if (threadIdx.x == 0) bad = 0;
    __syncthreads();
    long long v = ei[threadIdx.x];
    if (v < 0 || v >= NN) bad = 1;   // benign shared race, any writer sets 1
    __syncthreads();
    if (threadIdx.x == 0) g_is64 = bad ? 0 : 1;
}

__global__ void k_zero() {
    int i = blockIdx.x * blockDim.x + threadIdx.x;
    if (i < NN) g_deg[i] = 0;
    if (i == 0) g_alloc = 0;
}

__device__ __forceinline__ int load_idx(const void* ei, int pos) {
    if (g_is64) return (int)((const long long*)ei)[pos];
    return ((const int*)ei)[pos];
}

__global__ void k_hist(const void* __restrict__ ei) {
    int i = blockIdx.x * blockDim.x + threadIdx.x;
    if (i < NE) {
        int c = load_idx(ei, NE + i);          // col = second half
        if ((unsigned)c < NN) atomicAdd(&g_deg[c], 1);
    }
}

// Per-block inclusive scan + one atomicAdd per block to allocate a global
// contiguous range. Block-base order is arbitrary but each node's range is
// unique and contiguous, which is all the gather needs.
__global__ void k_offsets() {
    __shared__ int s[256];
    __shared__ int base;
    int tid = threadIdx.x;
    int n = blockIdx.x * 256 + tid;
    int v = (n < NN) ? g_deg[n] : 0;
    s[tid] = v;
    __syncthreads();
#pragma unroll
    for (int d = 1; d < 256; d <<= 1) {
        int y = (tid >= d) ? s[tid - d] : 0;
        __syncthreads();
        s[tid] += y;
        __syncthreads();
    }
    if (tid == 255) base = atomicAdd(&g_alloc, s[255]);
    __syncthreads();
    if (n < NN) g_off[n] = base + s[tid] - v;  // exclusive within block + base
}

__global__ void k_scatter(const void* __restrict__ ei) {
    int i = blockIdx.x * blockDim.x + threadIdx.x;
    if (i < NE) {
        int r = load_idx(ei, i);
        int c = load_idx(ei, NE + i);
        if ((unsigned)c < NN && (unsigned)r < NN) {
            int p = atomicAdd(&g_off[c], 1);   // g_off ends as "end" pointer
            g_rows[p] = r;
        }
    }
}

// g[n] = dinv[n] * (h[n] @ W).  Warp per node, lane = output column.
// h == nullptr means read from g_hbuf.
template <int DIN, int DOUT, int GS>
__global__ void k_transform(const float* __restrict__ h, int hstride,
                            const float* __restrict__ W) {
    __shared__ float sW[DIN * DOUT];
    for (int i = threadIdx.x; i < DIN * DOUT; i += blockDim.x) sW[i] = W[i];
    __syncthreads();

    int warp = (blockIdx.x * blockDim.x + threadIdx.x) >> 5;
    int lane = threadIdx.x & 31;
    if (warp >= NN) return;

    const float* hp = h ? h : g_hbuf;
    float hv = (lane < DIN) ? hp[warp * hstride + lane] : 0.f;

    float acc = 0.f;
#pragma unroll
    for (int k = 0; k < DIN; ++k) {
        float xv = __shfl_sync(0xffffffffu, hv, k);
        if (lane < DOUT) acc += xv * sW[k * DOUT + lane];
    }
    float dinv = rsqrtf((float)(g_deg[warp] + 1));
    if (lane < DOUT) g_gbuf[warp * GS + lane] = acc * dinv;
}

// out[c] = dinv[c] * (g[c] + sum_{e in CSR[c]} g[row_e]) + b.
// Warp per destination node, lane = feature. out == nullptr -> g_hbuf.
template <int DOUT, int GS, int OS>
__global__ void k_gather(float* __restrict__ out, const float* __restrict__ b) {
    int warp = (blockIdx.x * blockDim.x + threadIdx.x) >> 5;
    int lane = threadIdx.x & 31;
    if (warp >= NN) return;

    int end   = g_off[warp];       // end pointer after scatter
    int cnt   = g_deg[warp];
    int start = end - cnt;

    bool act = (lane < DOUT);
    float acc = act ? g_gbuf[warp * GS + lane] : 0.f;   // self loop term

    int e = start;
    for (; e + 4 <= end; e += 4) {
        int r0 = g_rows[e];
        int r1 = g_rows[e + 1];
        int r2 = g_rows[e + 2];
        int r3 = g_rows[e + 3];
        float v0 = act ? g_gbuf[r0 * GS + lane] : 0.f;
        float v1 = act ? g_gbuf[r1 * GS + lane] : 0.f;
        float v2 = act ? g_gbuf[r2 * GS + lane] : 0.f;
        float v3 = act ? g_gbuf[r3 * GS + lane] : 0.f;
        acc += ((v0 + v1) + (v2 + v3));
    }
    for (; e < end; ++e) {
        int r = g_rows[e];
        if (act) acc += g_gbuf[r * GS + lane];
    }

    float dinv = rsqrtf((float)(cnt + 1));
    float* op = out ? out : g_hbuf;
    if (act) op[warp * OS + lane] = acc * dinv + b[lane];
}

extern "C" void kernel_launch(void* const* d_in, const int* in_sizes, int n_in,
                              void* d_out, int out_size) {
    const float* x  = (const float*)d_in[0];
    const void*  ei = d_in[1];
    const float* W1 = (const float*)d_in[2];
    const float* b1 = (const float*)d_in[3];
    const float* W2 = (const float*)d_in[4];
    const float* b2 = (const float*)d_in[5];
    const float* W3 = (const float*)d_in[6];
    const float* b3 = (const float*)d_in[7];
    const float* W4 = (const float*)d_in[8];
    const float* b4 = (const float*)d_in[9];
    const float* W5 = (const float*)d_in[10];
    const float* b5 = (const float*)d_in[11];

    const int TB = 256;
    dim3 nodeGrid((NN + TB - 1) / TB);
    dim3 edgeGrid((NE + TB - 1) / TB);
    dim3 warpGrid((NN * 32 + TB - 1) / TB);  // warp per node

    // CSR build (re-done every launch; deterministic structure).
    k_detect<<<1, 256>>>((const long long*)ei);
    k_zero<<<nodeGrid, TB>>>();
    k_hist<<<edgeGrid, TB>>>(ei);
    k_offsets<<<nodeGrid, TB>>>();
    k_scatter<<<edgeGrid, TB>>>(ei);

    // Layer 1: din=8 -> 32
    k_transform<8, 32, 32><<<warpGrid, TB>>>(x, 8, W1);
    k_gather<32, 32, 32><<<warpGrid, TB>>>(nullptr, b1);
    // Layers 2-4: 32 -> 32
    k_transform<32, 32, 32><<<warpGrid, TB>>>(nullptr, 32, W2);
    k_gather<32, 32, 32><<<warpGrid, TB>>>(nullptr, b2);
    k_transform<32, 32, 32><<<warpGrid, TB>>>(nullptr, 32, W3);
    k_gather<32, 32, 32><<<warpGrid, TB>>>(nullptr, b3);
    k_transform<32, 32, 32><<<warpGrid, TB>>>(nullptr, 32, W4);
    k_gather<32, 32, 32><<<warpGrid, TB>>>(nullptr, b4);
    // Layer 5: 32 -> 3 (g rows padded to stride 4 for 16B alignment)
    k_transform<32, 3, 4><<<warpGrid, TB>>>(nullptr, 32, W5);
    k_gather<3, 4, 3><<<warpGrid, TB>>>((float*)d_out, b5);
}

// round 5
// speedup vs baseline: 1.1734x; 1.1734x over previous
#include <cuda_runtime.h>

// ---------------------------------------------------------------------------
// GCN 5-layer forward on GB300.
// Per-launch CSR build (hist -> block-scan offset alloc -> scatter).
// Hot chain: fused gather+next-transform kernels. Gather uses float4 with
// 8-lane groups: one LDG.128 warp instruction fetches 4 edges' feature rows
// (512B), maximizing L2 MLP. Epilogue reduces across groups via shfl,
// applies bias, and immediately computes the next layer's dinv*(h@W) row.
// NOTE: device-global buffers are ONLY referenced from device code (ping-pong
// direction is a template parameter) — passing __device__ symbols as host
// launch args was the round-3/4 correctness bug.
// ---------------------------------------------------------------------------

#define NN 100000
#define NE 1600000

__device__ int   g_deg[NN];         // edge in-degree (without self loop)
__device__ int   g_off[NN];         // start offsets, mutated to end by scatter
__device__ int   g_rows[NE];        // CSR row (source) indices grouped by col
__device__ float g_bufA[NN * 32];   // dinv-scaled transformed rows (ping)
__device__ float g_bufB[NN * 32];   // (pong)
__device__ int   g_alloc;           // offset range allocator
__device__ int   g_is64;            // 1 if edge_index is int64, 0 if int32

// Probe dtype: int32 data read as int64 packs two ids -> out-of-range values.
__global__ void k_detect(const long long* __restrict__ ei) {
    __shared__ int bad;
    if (threadIdx.x == 0) bad = 0;
    __syncthreads();
    long long v = ei[threadIdx.x];
    if (v < 0 || v >= NN) bad = 1;
    __syncthreads();
    if (threadIdx.x == 0) g_is64 = bad ? 0 : 1;
}

__global__ void k_zero() {
    int i = blockIdx.x * blockDim.x + threadIdx.x;
    if (i < NN) g_deg[i] = 0;
    if (i == 0) g_alloc = 0;
}

__device__ __forceinline__ int load_idx(const void* ei, int pos) {
    if (g_is64) return (int)((const long long*)ei)[pos];
    return ((const int*)ei)[pos];
}

__global__ void k_hist(const void* __restrict__ ei) {
    int i = blockIdx.x * blockDim.x + threadIdx.x;
    if (i < NE) {
        int c = load_idx(ei, NE + i);
        if ((unsigned)c < NN) atomicAdd(&g_deg[c], 1);
    }
}

// Per-block inclusive scan + one atomicAdd per block allocates a contiguous
// range; block order is arbitrary but each node's range is contiguous.
__global__ void k_offsets() {
    __shared__ int s[256];
    __shared__ int base;
    int tid = threadIdx.x;
    int n = blockIdx.x * 256 + tid;
    int v = (n < NN) ? g_deg[n] : 0;
    s[tid] = v;
    __syncthreads();
#pragma unroll
    for (int d = 1; d < 256; d <<= 1) {
        int y = (tid >= d) ? s[tid - d] : 0;
        __syncthreads();
        s[tid] += y;
        __syncthreads();
    }
    if (tid == 255) base = atomicAdd(&g_alloc, s[255]);
    __syncthreads();
    if (n < NN) g_off[n] = base + s[tid] - v;
}

__global__ void k_scatter(const void* __restrict__ ei) {
    int i = blockIdx.x * blockDim.x + threadIdx.x;
    if (i < NE) {
        int r = load_idx(ei, i);
        int c = load_idx(ei, NE + i);
        if ((unsigned)c < NN && (unsigned)r < NN) {
            int p = atomicAdd(&g_off[c], 1);   // g_off becomes "end" pointer
            g_rows[p] = r;
        }
    }
}

// First transform: g_bufA = dinv * (x @ W1), 8 -> 32. Warp per node.
__global__ void k_transform1(const float* __restrict__ x,
                             const float* __restrict__ W) {
    __shared__ float sW[8 * 32];
    for (int i = threadIdx.x; i < 8 * 32; i += blockDim.x) sW[i] = W[i];
    __syncthreads();

    int warp = (blockIdx.x * blockDim.x + threadIdx.x) >> 5;
    int lane = threadIdx.x & 31;
    if (warp >= NN) return;

    float hv = (lane < 8) ? x[warp * 8 + lane] : 0.f;
    float acc = 0.f;
#pragma unroll
    for (int k = 0; k < 8; ++k)
        acc += __shfl_sync(0xffffffffu, hv, k) * sW[k * 32 + lane];
    float dinv = rsqrtf((float)(g_deg[warp] + 1));
    g_bufA[warp * 32 + lane] = acc * dinv;
}

// Fused: aggregate src (dout=32) -> h = dinv*sum + bias, then next-layer
// transform g2 = dinv*(h @ W) written to dst with row stride OS.
// AtoB selects ping-pong direction (resolved in DEVICE code).
// Warp per node. 8-lane groups each own edge residues mod 4, so one LDG.128
// warp instruction covers 4 edges' rows.
template <int DNEXT, int OS, bool AtoB>
__global__ void k_fused(const float* __restrict__ bias,
                        const float* __restrict__ W) {
    const float* gsrc = AtoB ? g_bufA : g_bufB;
    float*       gdst = AtoB ? g_bufB : g_bufA;

    __shared__ float sW[32 * DNEXT];
    for (int i = threadIdx.x; i < 32 * DNEXT; i += blockDim.x) sW[i] = W[i];
    __syncthreads();

    int warp = (blockIdx.x * blockDim.x + threadIdx.x) >> 5;
    int lane = threadIdx.x & 31;
    if (warp >= NN) return;

    int grp = lane >> 3;          // edge slot within a 4-edge pack
    int fl  = lane & 7;           // float4 column within the 32-float row
    int end   = g_off[warp];
    int cnt   = g_deg[warp];
    int start = end - cnt;

    const float4* src4 = (const float4*)gsrc;

    // Self-loop term contributed once by group 0.
    float4 acc = make_float4(0.f, 0.f, 0.f, 0.f);
    if (grp == 0) acc = src4[warp * 8 + fl];

    int e = start + grp;
    for (; e + 4 < end; e += 8) {             // 2 edges per group per iter
        int r0 = g_rows[e];
        int r1 = g_rows[e + 4];
        float4 v0 = src4[r0 * 8 + fl];
        float4 v1 = src4[r1 * 8 + fl];
        acc.x += v0.x + v1.x; acc.y += v0.y + v1.y;
        acc.z += v0.z + v1.z; acc.w += v0.w + v1.w;
    }
    if (e < end) {
        int r = g_rows[e];
        float4 v = src4[r * 8 + fl];
        acc.x += v.x; acc.y += v.y; acc.z += v.z; acc.w += v.w;
    }

    // Reduce across the 4 groups (butterfly): every lane gets the column sum.
#pragma unroll
    for (int d = 8; d <= 16; d <<= 1) {
        acc.x += __shfl_xor_sync(0xffffffffu, acc.x, d);
        acc.y += __shfl_xor_sync(0xffffffffu, acc.y, d);
        acc.z += __shfl_xor_sync(0xffffffffu, acc.z, d);
        acc.w += __shfl_xor_sync(0xffffffffu, acc.w, d);
    }

    // Redistribute: lane j takes feature j (component j&3 of float4 j>>2).
    int srcl = lane >> 2;
    float t0 = __shfl_sync(0xffffffffu, acc.x, srcl);
    float t1 = __shfl_sync(0xffffffffu, acc.y, srcl);
    float t2 = __shfl_sync(0xffffffffu, acc.z, srcl);
    float t3 = __shfl_sync(0xffffffffu, acc.w, srcl);
    int c = lane & 3;
    float s = (c == 0) ? t0 : (c == 1) ? t1 : (c == 2) ? t2 : t3;

    float dinv = rsqrtf((float)(cnt + 1));
    float h = s * dinv + bias[lane];          // this layer's output feature

    // Next layer transform: g2_j = dinv * sum_k h_k * W[k][j]
    float a2 = 0.f;
#pragma unroll
    for (int k = 0; k < 32; ++k) {
        float hk = __shfl_sync(0xffffffffu, h, k);
        if (lane < DNEXT) a2 += hk * sW[k * DNEXT + lane];
    }
    if (lane < DNEXT) gdst[warp * OS + lane] = a2 * dinv;
}

// Final aggregation over stride-4 rows in g_bufA (dout=3): 1 lane per edge,
// 32 edges per warp instruction.
__global__ void k_final(float* __restrict__ out,
                        const float* __restrict__ bias) {
    int warp = (blockIdx.x * blockDim.x + threadIdx.x) >> 5;
    int lane = threadIdx.x & 31;
    if (warp >= NN) return;

    int end   = g_off[warp];
    int cnt   = g_deg[warp];
    int start = end - cnt;

    const float4* src4 = (const float4*)g_bufA;
    float4 acc = make_float4(0.f, 0.f, 0.f, 0.f);
    if (lane == 0) {                           // self loop
        float4 v = src4[warp];
        acc.x = v.x; acc.y = v.y; acc.z = v.z;
    }

    for (int e = start + lane; e < end; e += 32) {
        int r = g_rows[e];
        float4 v = src4[r];
        acc.x += v.x; acc.y += v.y; acc.z += v.z;
    }
#pragma unroll
    for (int d = 1; d <= 16; d <<= 1) {
        acc.x += __shfl_xor_sync(0xffffffffu, acc.x, d);
        acc.y += __shfl_xor_sync(0xffffffffu, acc.y, d);
        acc.z += __shfl_xor_sync(0xffffffffu, acc.z, d);
    }
    if (lane == 0) {
        float dinv = rsqrtf((float)(cnt + 1));
        out[warp * 3 + 0] = acc.x * dinv + bias[0];
        out[warp * 3 + 1] = acc.y * dinv + bias[1];
        out[warp * 3 + 2] = acc.z * dinv + bias[2];
    }
}

extern "C" void kernel_launch(void* const* d_in, const int* in_sizes, int n_in,
                              void* d_out, int out_size) {
    const float* x  = (const float*)d_in[0];
    const void*  ei = d_in[1];
    const float* W1 = (const float*)d_in[2];
    const float* b1 = (const float*)d_in[3];
    const float* W2 = (const float*)d_in[4];
    const float* b2 = (const float*)d_in[5];
    const float* W3 = (const float*)d_in[6];
    const float* b3 = (const float*)d_in[7];
    const float* W4 = (const float*)d_in[8];
    const float* b4 = (const float*)d_in[9];
    const float* W5 = (const float*)d_in[10];
    const float* b5 = (const float*)d_in[11];

    const int TB = 256;
    dim3 nodeGrid((NN + TB - 1) / TB);
    dim3 edgeGrid((NE + TB - 1) / TB);
    dim3 warpGrid((NN * 32 + TB - 1) / TB);  // warp per node

    // CSR build (re-done every launch; deterministic structure).
    k_detect<<<1, 256>>>((const long long*)ei);
    k_zero<<<nodeGrid, TB>>>();
    k_hist<<<edgeGrid, TB>>>(ei);
    k_offsets<<<nodeGrid, TB>>>();
    k_scatter<<<edgeGrid, TB>>>(ei);

    k_transform1<<<warpGrid, TB>>>(x, W1);                    // x -> A
    k_fused<32, 32, true ><<<warpGrid, TB>>>(b1, W2);         // A -> B
    k_fused<32, 32, false><<<warpGrid, TB>>>(b2, W3);         // B -> A
    k_fused<32, 32, true ><<<warpGrid, TB>>>(b3, W4);         // A -> B
    k_fused<3, 4, false><<<warpGrid, TB>>>(b4, W5);           // B -> A (stride 4)
    k_final<<<warpGrid, TB>>>((float*)d_out, b5);
}

// round 6
// speedup vs baseline: 1.1753x; 1.0016x over previous
#include <cuda_runtime.h>

// ---------------------------------------------------------------------------
// GCN 5-layer forward on GB300.
// Per-launch CSR build (hist -> block-scan offset alloc -> scatter).
// Hot chain: fused gather+next-transform kernels. Gather uses float4 with
// 8-lane groups; each group issues 4 independent LDG.128s per iteration
// (16 edges' rows in flight per warp). Epilogue reduces via shfl, applies
// bias, and computes the next layer's dinv*(h@W) row in-register.
// Edge indices are always read as 32-bit (low word of int64 when needed).
// Device-global buffers are referenced from device code only.
// ---------------------------------------------------------------------------

#define NN 100000
#define NE 1600000

__device__ int   g_deg[NN];         // edge in-degree (without self loop)
__device__ int   g_off[NN];         // start offsets, mutated to end by scatter
__device__ int   g_rows[NE];        // CSR row (source) indices grouped by col
__device__ float g_bufA[NN * 32];   // dinv-scaled transformed rows (ping)
__device__ float g_bufB[NN * 32];   // (pong)
__device__ int   g_alloc;           // offset range allocator
__device__ int   g_is64;            // 1 if edge_index is int64, 0 if int32

// Zero degrees + (block 0) probe dtype: int32 data read as int64 packs two
// ids per word -> out-of-range values.
__global__ void k_zero(const long long* __restrict__ ei) {
    int i = blockIdx.x * blockDim.x + threadIdx.x;
    if (i < NN) g_deg[i] = 0;
    if (blockIdx.x == 0) {
        __shared__ int bad;
        if (threadIdx.x == 0) { bad = 0; g_alloc = 0; }
        __syncthreads();
        long long v = ei[threadIdx.x];
        if (v < 0 || v >= NN) bad = 1;
        __syncthreads();
        if (threadIdx.x == 0) g_is64 = bad ? 0 : 1;
    }
}

// ids < 2^31: for int64 input read only the low 32-bit word.
__device__ __forceinline__ int load_idx(const int* ei32, int pos, int is64) {
    return is64 ? ei32[2 * pos] : ei32[pos];
}

__global__ void k_hist(const int* __restrict__ ei32) {
    int i = blockIdx.x * blockDim.x + threadIdx.x;
    if (i < NE) {
        int c = load_idx(ei32, NE + i, g_is64);
        if ((unsigned)c < NN) atomicAdd(&g_deg[c], 1);
    }
}

// Per-block inclusive scan + one atomicAdd per block allocates a contiguous
// range; block order is arbitrary but each node's range is contiguous.
__global__ void k_offsets() {
    __shared__ int s[256];
    __shared__ int base;
    int tid = threadIdx.x;
    int n = blockIdx.x * 256 + tid;
    int v = (n < NN) ? g_deg[n] : 0;
    s[tid] = v;
    __syncthreads();
#pragma unroll
    for (int d = 1; d < 256; d <<= 1) {
        int y = (tid >= d) ? s[tid - d] : 0;
        __syncthreads();
        s[tid] += y;
        __syncthreads();
    }
    if (tid == 255) base = atomicAdd(&g_alloc, s[255]);
    __syncthreads();
    if (n < NN) g_off[n] = base + s[tid] - v;
}

__global__ void k_scatter(const int* __restrict__ ei32) {
    int i = blockIdx.x * blockDim.x + threadIdx.x;
    if (i < NE) {
        int is64 = g_is64;
        int r = load_idx(ei32, i, is64);
        int c = load_idx(ei32, NE + i, is64);
        if ((unsigned)c < NN && (unsigned)r < NN) {
            int p = atomicAdd(&g_off[c], 1);   // g_off becomes "end" pointer
            g_rows[p] = r;
        }
    }
}

// First transform: g_bufA = dinv * (x @ W1), 8 -> 32. Warp per node.
__global__ void k_transform1(const float* __restrict__ x,
                             const float* __restrict__ W) {
    __shared__ float sW[8 * 32];
    for (int i = threadIdx.x; i < 8 * 32; i += blockDim.x) sW[i] = W[i];
    __syncthreads();

    int warp = (blockIdx.x * blockDim.x + threadIdx.x) >> 5;
    int lane = threadIdx.x & 31;
    if (warp >= NN) return;

    float hv = (lane < 8) ? x[warp * 8 + lane] : 0.f;
    float acc = 0.f;
#pragma unroll
    for (int k = 0; k < 8; ++k)
        acc += __shfl_sync(0xffffffffu, hv, k) * sW[k * 32 + lane];
    float dinv = rsqrtf((float)(g_deg[warp] + 1));
    g_bufA[warp * 32 + lane] = acc * dinv;
}

// Fused: aggregate src (dout=32) -> h = dinv*sum + bias, then next-layer
// transform g2 = dinv*(h @ W) written with row stride OS. AtoB selects the
// ping-pong direction in device code. Warp per node; 8-lane groups own edge
// residues mod 4; each iteration issues 4 independent LDG.128 per group.
template <int DNEXT, int OS, bool AtoB>
__global__ void k_fused(const float* __restrict__ bias,
                        const float* __restrict__ W) {
    const float* gsrc = AtoB ? g_bufA : g_bufB;
    float*       gdst = AtoB ? g_bufB : g_bufA;

    __shared__ float sW[32 * DNEXT];
    for (int i = threadIdx.x; i < 32 * DNEXT; i += blockDim.x) sW[i] = W[i];
    __syncthreads();

    int warp = (blockIdx.x * blockDim.x + threadIdx.x) >> 5;
    int lane = threadIdx.x & 31;
    if (warp >= NN) return;

    int grp = lane >> 3;          // edge residue within a 4-edge pack
    int fl  = lane & 7;           // float4 column within the 32-float row
    int end   = g_off[warp];
    int cnt   = g_deg[warp];
    int start = end - cnt;

    const float4* src4 = (const float4*)gsrc;

    // Self-loop term contributed once by group 0.
    float4 acc = make_float4(0.f, 0.f, 0.f, 0.f);
    if (grp == 0) acc = src4[warp * 8 + fl];

    int e = start + grp;
    // 4 edges per group per iteration: 16 independent 128B lines per warp.
    for (; e + 12 < end; e += 16) {
        int r0 = g_rows[e];
        int r1 = g_rows[e + 4];
        int r2 = g_rows[e + 8];
        int r3 = g_rows[e + 12];
        float4 v0 = src4[r0 * 8 + fl];
        float4 v1 = src4[r1 * 8 + fl];
        float4 v2 = src4[r2 * 8 + fl];
        float4 v3 = src4[r3 * 8 + fl];
        acc.x += (v0.x + v1.x) + (v2.x + v3.x);
        acc.y += (v0.y + v1.y) + (v2.y + v3.y);
        acc.z += (v0.z + v1.z) + (v2.z + v3.z);
        acc.w += (v0.w + v1.w) + (v2.w + v3.w);
    }
    for (; e < end; e += 4) {
        int r = g_rows[e];
        float4 v = src4[r * 8 + fl];
        acc.x += v.x; acc.y += v.y; acc.z += v.z; acc.w += v.w;
    }

    // Reduce across the 4 groups (butterfly): every lane gets the column sum.
#pragma unroll
    for (int d = 8; d <= 16; d <<= 1) {
        acc.x += __shfl_xor_sync(0xffffffffu, acc.x, d);
        acc.y += __shfl_xor_sync(0xffffffffu, acc.y, d);
        acc.z += __shfl_xor_sync(0xffffffffu, acc.z, d);
        acc.w += __shfl_xor_sync(0xffffffffu, acc.w, d);
    }

    // Redistribute: lane j takes feature j (component j&3 of float4 j>>2).
    int srcl = lane >> 2;
    float t0 = __shfl_sync(0xffffffffu, acc.x, srcl);
    float t1 = __shfl_sync(0xffffffffu, acc.y, srcl);
    float t2 = __shfl_sync(0xffffffffu, acc.z, srcl);
    float t3 = __shfl_sync(0xffffffffu, acc.w, srcl);
    int c = lane & 3;
    float s = (c == 0) ? t0 : (c == 1) ? t1 : (c == 2) ? t2 : t3;

    float dinv = rsqrtf((float)(cnt + 1));
    float h = s * dinv + bias[lane];          // this layer's output feature

    // Next layer transform: g2_j = dinv * sum_k h_k * W[k][j]
    float a2 = 0.f;
#pragma unroll
    for (int k = 0; k < 32; ++k) {
        float hk = __shfl_sync(0xffffffffu, h, k);
        if (lane < DNEXT) a2 += hk * sW[k * DNEXT + lane];
    }
    if (lane < DNEXT) gdst[warp * OS + lane] = a2 * dinv;
}

// Final aggregation over stride-4 rows in g_bufA (dout=3): 1 lane per edge.
__global__ void k_final(float* __restrict__ out,
                        const float* __restrict__ bias) {
    int warp = (blockIdx.x * blockDim.x + threadIdx.x) >> 5;
    int lane = threadIdx.x & 31;
    if (warp >= NN) return;

    int end   = g_off[warp];
    int cnt   = g_deg[warp];
    int start = end - cnt;

    const float4* src4 = (const float4*)g_bufA;
    float4 acc = make_float4(0.f, 0.f, 0.f, 0.f);
    if (lane == 0) {                           // self loop
        float4 v = src4[warp];
        acc.x = v.x; acc.y = v.y; acc.z = v.z;
    }

    for (int e = start + lane; e < end; e += 32) {
        int r = g_rows[e];
        float4 v = src4[r];
        acc.x += v.x; acc.y += v.y; acc.z += v.z;
    }
#pragma unroll
    for (int d = 1; d <= 16; d <<= 1) {
        acc.x += __shfl_xor_sync(0xffffffffu, acc.x, d);
        acc.y += __shfl_xor_sync(0xffffffffu, acc.y, d);
        acc.z += __shfl_xor_sync(0xffffffffu, acc.z, d);
    }
    if (lane == 0) {
        float dinv = rsqrtf((float)(cnt + 1));
        out[warp * 3 + 0] = acc.x * dinv + bias[0];
        out[warp * 3 + 1] = acc.y * dinv + bias[1];
        out[warp * 3 + 2] = acc.z * dinv + bias[2];
    }
}

extern "C" void kernel_launch(void* const* d_in, const int* in_sizes, int n_in,
                              void* d_out, int out_size) {
    const float* x    = (const float*)d_in[0];
    const int*   ei32 = (const int*)d_in[1];
    const float* W1 = (const float*)d_in[2];
    const float* b1 = (const float*)d_in[3];
    const float* W2 = (const float*)d_in[4];
    const float* b2 = (const float*)d_in[5];
    const float* W3 = (const float*)d_in[6];
    const float* b3 = (const float*)d_in[7];
    const float* W4 = (const float*)d_in[8];
    const float* b4 = (const float*)d_in[9];
    const float* W5 = (const float*)d_in[10];
    const float* b5 = (const float*)d_in[11];

    const int TB = 256;
    dim3 nodeGrid((NN + TB - 1) / TB);
    dim3 edgeGrid((NE + TB - 1) / TB);
    dim3 warpGrid((NN * 32 + TB - 1) / TB);  // warp per node

    // CSR build (re-done every launch; deterministic structure).
    k_zero<<<nodeGrid, TB>>>((const long long*)ei32);   // launch 0
    k_hist<<<edgeGrid, TB>>>(ei32);                     // launch 1
    k_offsets<<<nodeGrid, TB>>>();                      // launch 2
    k_scatter<<<edgeGrid, TB>>>(ei32);                  // launch 3

    k_transform1<<<warpGrid, TB>>>(x, W1);              // launch 4: x -> A
    k_fused<32, 32, true ><<<warpGrid, TB>>>(b1, W2);   // launch 5: A -> B (profiled)
    k_fused<32, 32, false><<<warpGrid, TB>>>(b2, W3);   // B -> A
    k_fused<32, 32, true ><<<warpGrid, TB>>>(b3, W4);   // A -> B
    k_fused<3, 4, false><<<warpGrid, TB>>>(b4, W5);     // B -> A (stride 4)
    k_final<<<warpGrid, TB>>>((float*)d_out, b5);
}